// round 11
// baseline (speedup 1.0000x reference)
#include <cuda_runtime.h>
#include <cuda_bf16.h>
#include <cstdint>
#include <math.h>

#define C_DIM    40
#define VPR      10                   // float4 vectors per row
#define VPAD     11                   // padded row pitch in float4 -> conflict-free LDS.128
#define THREADS  128
#define ROWS     128                  // rows per block == threads per block

__global__ void init_out_kernel(float* out) {
    out[0] = 0.0f;
}

__global__ __launch_bounds__(THREADS) void hier_loss_kernel(
    const float* __restrict__ logits,   // [B, 40]
    const int*   __restrict__ labels,   // [B]
    const float* __restrict__ dis,      // [40, 40]
    float* __restrict__ out,            // out[0]=loss, out[1..B]=distance_factor
    int B)
{
    __shared__ float4 s4[ROWS * VPAD];          // 128*11*16 = 22528 B -> 10 blocks/SM
    __shared__ float  wsum[THREADS / 32];

    const int tid      = threadIdx.x;
    const int blockRow = blockIdx.x * ROWS;

    // ---- stage 128 rows (1280 float4) coalesced ----
    {
        const float4* src = reinterpret_cast<const float4*>(logits + (long long)blockRow * C_DIM);
        #pragma unroll
        for (int j = 0; j < ROWS * VPR / THREADS; j++) {   // 10 iterations
            int i = tid + j * THREADS;                      // 0..1279
            float4 q = __ldg(src + i);
            int r = i / VPR;                                // const-div -> mul/shift
            int c = i - r * VPR;
            s4[r * VPAD + c] = q;
        }
    }
    __syncthreads();

    // ---- each thread consumes one row via 10x conflict-free LDS.128 ----
    float contrib = 0.0f;
    const int row = blockRow + tid;
    if (row < B) {
        const float4* rowp = s4 + tid * VPAD;

        float v[C_DIM];
        #pragma unroll
        for (int k = 0; k < VPR; k++) {
            float4 q = rowp[k];
            v[4 * k + 0] = q.x;
            v[4 * k + 1] = q.y;
            v[4 * k + 2] = q.z;
            v[4 * k + 3] = q.w;
        }

        // ---- tree max (8 lanes then log-reduce) ----
        float m[8];
        #pragma unroll
        for (int i = 0; i < 8; i++) m[i] = v[i];
        #pragma unroll
        for (int i = 8; i < C_DIM; i++) m[i & 7] = fmaxf(m[i & 7], v[i]);
        m[0] = fmaxf(m[0], m[4]);
        m[1] = fmaxf(m[1], m[5]);
        m[2] = fmaxf(m[2], m[6]);
        m[3] = fmaxf(m[3], m[7]);
        m[0] = fmaxf(m[0], m[2]);
        m[1] = fmaxf(m[1], m[3]);
        const float mx = fmaxf(m[0], m[1]);

        // ---- first-occurrence argmax: min-index among v[i]==mx (tree) ----
        int a[8];
        #pragma unroll
        for (int i = 0; i < 8; i++) a[i] = (v[i] == mx) ? i : 1024;
        #pragma unroll
        for (int i = 8; i < C_DIM; i++) {
            int cand = (v[i] == mx) ? i : 1024;
            a[i & 7] = min(a[i & 7], cand);
        }
        a[0] = min(a[0], a[4]);
        a[1] = min(a[1], a[5]);
        a[2] = min(a[2], a[6]);
        a[3] = min(a[3], a[7]);
        a[0] = min(a[0], a[2]);
        a[1] = min(a[1], a[3]);
        const int am = min(a[0], a[1]);

        // ---- sum exp(x - max), 4 accumulators ----
        float s0 = 0.0f, s1 = 0.0f, s2 = 0.0f, s3 = 0.0f;
        #pragma unroll
        for (int i = 0; i < C_DIM; i += 4) {
            s0 += __expf(v[i + 0] - mx);
            s1 += __expf(v[i + 1] - mx);
            s2 += __expf(v[i + 2] - mx);
            s3 += __expf(v[i + 3] - mx);
        }
        const float ssum = (s0 + s1) + (s2 + s3);

        int lbl = __ldg(labels + row);
        float xl = reinterpret_cast<const float*>(rowp)[lbl];   // scalar LDS

        float ce = __logf(ssum) + mx - xl;
        float df = __ldg(dis + lbl * C_DIM + am) + 0.5f;
        out[1 + row] = df;
        contrib = ce * df;
    }

    // ---- warp, then block reduction; one atomic per block ----
    #pragma unroll
    for (int off = 16; off > 0; off >>= 1)
        contrib += __shfl_xor_sync(0xFFFFFFFFu, contrib, off);

    const int lane = tid & 31;
    const int warp = tid >> 5;
    if (lane == 0) wsum[warp] = contrib;
    __syncthreads();

    if (warp == 0) {
        float t = (lane < THREADS / 32) ? wsum[lane] : 0.0f;
        #pragma unroll
        for (int off = 2; off > 0; off >>= 1)
            t += __shfl_xor_sync(0xFFFFFFFFu, t, off);
        if (lane == 0)
            atomicAdd(out, t * (1.0f / (float)B));
    }
}

extern "C" void kernel_launch(void* const* d_in, const int* in_sizes, int n_in,
                              void* d_out, int out_size) {
    const float* logits = (const float*)d_in[0];
    const int*   labels = (const int*)d_in[1];
    const float* dis    = (const float*)d_in[2];
    float* out = (float*)d_out;

    int B = in_sizes[1];

    init_out_kernel<<<1, 1>>>(out);

    int blocks = (B + ROWS - 1) / ROWS;
    hier_loss_kernel<<<blocks, THREADS>>>(logits, labels, dis, out, B);
}

// round 12
// speedup vs baseline: 1.1373x; 1.1373x over previous
#include <cuda_runtime.h>
#include <cuda_bf16.h>
#include <cstdint>
#include <math.h>

#define C_DIM    40
#define VPR      10                   // float4 vectors per row
#define VPAD     11                   // padded row pitch (float4) -> conflict-free LDS.128
#define THREADS  256
#define ROWS     256                  // rows per block == threads per block

__global__ void init_out_kernel(float* out) {
    out[0] = 0.0f;
}

__device__ __forceinline__ void cp_async16(unsigned int dst_smem, const void* src) {
    asm volatile("cp.async.cg.shared.global [%0], [%1], 16;\n"
                 :: "r"(dst_smem), "l"(src) : "memory");
}

__global__ __launch_bounds__(THREADS) void hier_loss_kernel(
    const float* __restrict__ logits,   // [B, 40]
    const int*   __restrict__ labels,   // [B]
    const float* __restrict__ dis,      // [40, 40]
    float* __restrict__ out,            // out[0]=loss, out[1..B]=distance_factor
    int B)
{
    __shared__ float4 s4[ROWS * VPAD];  // 256*11*16 = 45056 B -> 5 blocks/SM
    __shared__ float  wsum[THREADS / 32];

    const int tid      = threadIdx.x;
    const int blockRow = blockIdx.x * ROWS;
    const int row      = blockRow + tid;

    // ---- stage 256 rows (2560 float4) via cp.async.cg (L1-bypass, no reg state) ----
    {
        const char* src = (const char*)(logits + (long long)blockRow * C_DIM);
        unsigned int sbase = (unsigned int)__cvta_generic_to_shared(s4);
        #pragma unroll
        for (int j = 0; j < ROWS * VPR / THREADS; j++) {   // 10 iterations
            int i = tid + j * THREADS;                      // 0..2559
            int r = i / VPR;                                // const-div -> mul/shift
            int c = i - r * VPR;
            cp_async16(sbase + (unsigned int)(r * VPAD + c) * 16u,
                       src + (size_t)i * 16u);
        }
        asm volatile("cp.async.commit_group;\n" ::: "memory");
    }

    // overlap: fetch this thread's label while the async fill is in flight
    int lbl = (row < B) ? __ldg(labels + row) : 0;

    asm volatile("cp.async.wait_group 0;\n" ::: "memory");
    __syncthreads();

    // ---- each thread consumes one row via 10x conflict-free LDS.128 ----
    float contrib = 0.0f;
    if (row < B) {
        const float4* rowp = s4 + tid * VPAD;

        float v[C_DIM];
        #pragma unroll
        for (int k = 0; k < VPR; k++) {
            float4 q = rowp[k];
            v[4 * k + 0] = q.x;
            v[4 * k + 1] = q.y;
            v[4 * k + 2] = q.z;
            v[4 * k + 3] = q.w;
        }

        // max + argmax (first occurrence)
        float mx = v[0];
        int   am = 0;
        #pragma unroll
        for (int i = 1; i < C_DIM; i++) {
            if (v[i] > mx) { mx = v[i]; am = i; }
        }

        // sum exp(x - max)
        float ssum = 0.0f;
        #pragma unroll
        for (int i = 0; i < C_DIM; i++) {
            ssum += __expf(v[i] - mx);
        }

        float xl = reinterpret_cast<const float*>(rowp)[lbl];   // scalar LDS

        float ce = __logf(ssum) + mx - xl;
        float df = __ldg(dis + lbl * C_DIM + am) + 0.5f;
        out[1 + row] = df;
        contrib = ce * df;
    }

    // ---- warp, then block reduction; one atomic per block ----
    #pragma unroll
    for (int off = 16; off > 0; off >>= 1)
        contrib += __shfl_xor_sync(0xFFFFFFFFu, contrib, off);

    const int lane = tid & 31;
    const int warp = tid >> 5;
    if (lane == 0) wsum[warp] = contrib;
    __syncthreads();

    if (warp == 0) {
        float t = (lane < THREADS / 32) ? wsum[lane] : 0.0f;
        #pragma unroll
        for (int off = 4; off > 0; off >>= 1)
            t += __shfl_xor_sync(0xFFFFFFFFu, t, off);
        if (lane == 0)
            atomicAdd(out, t * (1.0f / (float)B));
    }
}

extern "C" void kernel_launch(void* const* d_in, const int* in_sizes, int n_in,
                              void* d_out, int out_size) {
    const float* logits = (const float*)d_in[0];
    const int*   labels = (const int*)d_in[1];
    const float* dis    = (const float*)d_in[2];
    float* out = (float*)d_out;

    int B = in_sizes[1];

    init_out_kernel<<<1, 1>>>(out);

    int blocks = (B + ROWS - 1) / ROWS;
    hier_loss_kernel<<<blocks, THREADS>>>(logits, labels, dis, out, B);
}

// round 13
// speedup vs baseline: 1.1837x; 1.0408x over previous
#include <cuda_runtime.h>
#include <cuda_bf16.h>
#include <cstdint>
#include <math.h>

#define C_DIM    40
#define VPR      10                        // float4 per row (no padding)
#define TROWS    128                       // rows per stage
#define NVEC     (TROWS * VPR)             // 1280 float4 per stage
#define THREADS  256
#define WARPS    (THREADS / 32)
#define SM_COUNT 148
#define BLOCKS_PER_SM 5
#define GRID     (SM_COUNT * BLOCKS_PER_SM)   // 740 persistent blocks

__device__ int g_tile_ctr;

__global__ void init_kernel(float* out) {
    out[0] = 0.0f;
    g_tile_ctr = 0;
}

__device__ __forceinline__ void cp_async16(unsigned int dst_smem, const void* src) {
    asm volatile("cp.async.cg.shared.global [%0], [%1], 16;\n"
                 :: "r"(dst_smem), "l"(src) : "memory");
}

__global__ __launch_bounds__(THREADS) void hier_loss_kernel(
    const float* __restrict__ logits,   // [B, 40]
    const int*   __restrict__ labels,   // [B]
    const float* __restrict__ dis,      // [40, 40]
    float* __restrict__ out,            // out[0]=loss, out[1..B]=distance_factor
    int B, int NT)
{
    __shared__ float4 s4[2][NVEC];      // 2 * 1280 * 16 = 40960 B -> 5 blocks/SM
    __shared__ int   s_t;
    __shared__ float wsum[WARPS];

    const int tid  = threadIdx.x;
    const int lane = tid & 31;
    const int warp = tid >> 5;
    const int r    = tid >> 1;          // row within stage (0..127)
    const int sub  = tid & 1;           // half of row (0 -> idx 0..19, 1 -> idx 20..39)

    const unsigned int sbase = (unsigned int)__cvta_generic_to_shared(&s4[0][0]);

    // ---- stage loader: tile t -> buffer b (identity addressing, zero ALU) ----
    auto prefetch = [&](int t, int b) {
        if (t < NT) {
            long rowsLeft = (long)B - (long)t * TROWS;
            int  nv = (rowsLeft >= TROWS) ? NVEC : (int)rowsLeft * VPR;
            const char* src = (const char*)(logits + (long)t * TROWS * C_DIM);
            unsigned int sb = sbase + (unsigned int)b * (NVEC * 16u);
            #pragma unroll
            for (int j = 0; j < NVEC / THREADS; j++) {   // 5
                int i = tid + j * THREADS;
                if (i < nv)
                    cp_async16(sb + (unsigned int)i * 16u, src + (size_t)i * 16u);
            }
        }
        asm volatile("cp.async.commit_group;\n" ::: "memory");
    };

    auto fetch_label = [&](int t) -> int {
        long row = (long)t * TROWS + r;
        return (t < NT && row < B) ? __ldg(labels + row) : 0;
    };

    // ---- prologue: grab two tiles ----
    if (tid == 0) s_t = atomicAdd(&g_tile_ctr, 1);
    __syncthreads();
    int t_cur = s_t;
    if (tid == 0) s_t = atomicAdd(&g_tile_ctr, 1);
    __syncthreads();
    int t_nxt = s_t;

    prefetch(t_cur, 0);
    int lbl_cur = fetch_label(t_cur);
    int cur = 0;

    float acc = 0.0f;

    while (t_cur < NT) {
        // issue next stage + grab tile after next
        prefetch(t_nxt, cur ^ 1);
        int lbl_nxt = fetch_label(t_nxt);
        if (tid == 0) s_t = atomicAdd(&g_tile_ctr, 1);

        asm volatile("cp.async.wait_group 1;\n" ::: "memory");
        __syncthreads();                       // buf[cur] + s_t visible

        // ---- compute 128 rows from buf[cur], 2 threads per row ----
        {
            const float4* basev = &s4[cur][0] + r * VPR + sub * 5;
            float v[20];
            #pragma unroll
            for (int k = 0; k < 5; k++) {
                float4 q = basev[k];
                v[4 * k + 0] = q.x;
                v[4 * k + 1] = q.y;
                v[4 * k + 2] = q.z;
                v[4 * k + 3] = q.w;
            }

            // local max/argmax (first occurrence), global index = sub*20 + i
            float mx = v[0];
            int   am = 0;
            #pragma unroll
            for (int i = 1; i < 20; i++) {
                if (v[i] > mx) { mx = v[i]; am = i; }
            }
            am += sub * 20;

            // merge pair (unconditional shuffles; tie -> smaller index)
            float omx = __shfl_xor_sync(0xFFFFFFFFu, mx, 1);
            int   oam = __shfl_xor_sync(0xFFFFFFFFu, am, 1);
            if (omx > mx || (omx == mx && oam < am)) { mx = omx; am = oam; }

            // exp-sum with final max
            float ssum = 0.0f;
            #pragma unroll
            for (int i = 0; i < 20; i++) {
                ssum += __expf(v[i] - mx);
            }
            ssum += __shfl_xor_sync(0xFFFFFFFFu, ssum, 1);

            long row = (long)t_cur * TROWS + r;
            if (sub == 0 && row < B) {
                // x[label] directly from smem (row is 40 contiguous floats)
                float xl = reinterpret_cast<const float*>(&s4[cur][0])[r * C_DIM + lbl_cur];
                float ce = __logf(ssum) + mx - xl;
                float df = __ldg(dis + lbl_cur * C_DIM + am) + 0.5f;
                out[1 + row] = df;
                acc += ce * df;
            }
        }

        int t_n2 = s_t;
        __syncthreads();                       // done reading buf[cur] / s_t

        t_cur = t_nxt;  lbl_cur = lbl_nxt;
        t_nxt = t_n2;
        cur ^= 1;
    }

    // ---- final reduction: warp, block, one atomic per block ----
    #pragma unroll
    for (int off = 16; off > 0; off >>= 1)
        acc += __shfl_xor_sync(0xFFFFFFFFu, acc, off);

    if (lane == 0) wsum[warp] = acc;
    __syncthreads();

    if (warp == 0) {
        float t = (lane < WARPS) ? wsum[lane] : 0.0f;
        #pragma unroll
        for (int off = 4; off > 0; off >>= 1)
            t += __shfl_xor_sync(0xFFFFFFFFu, t, off);
        if (lane == 0)
            atomicAdd(out, t * (1.0f / (float)B));
    }
}

extern "C" void kernel_launch(void* const* d_in, const int* in_sizes, int n_in,
                              void* d_out, int out_size) {
    const float* logits = (const float*)d_in[0];
    const int*   labels = (const int*)d_in[1];
    const float* dis    = (const float*)d_in[2];
    float* out = (float*)d_out;

    int B  = in_sizes[1];
    int NT = (B + TROWS - 1) / TROWS;

    init_kernel<<<1, 1>>>(out);
    hier_loss_kernel<<<GRID, THREADS>>>(logits, labels, dis, out, B, NT);
}

// round 14
// speedup vs baseline: 1.1918x; 1.0068x over previous
#include <cuda_runtime.h>
#include <cuda_bf16.h>
#include <cstdint>
#include <math.h>

#define C_DIM    40
#define VPR      10                        // float4 per row (no padding)
#define TROWS    128                       // rows per stage
#define NVEC     (TROWS * VPR)             // 1280 float4 per stage
#define THREADS  256
#define WARPS    (THREADS / 32)
#define SM_COUNT 148
#define BLOCKS_PER_SM 5
#define GRID     (SM_COUNT * BLOCKS_PER_SM)   // 740 persistent blocks

__device__ float g_partials[GRID];
__device__ int   g_tile_ctr;   // zero-initialized at load; reset to 0 by last block each launch
__device__ int   g_done_ctr;   // ditto

__device__ __forceinline__ void cp_async16(unsigned int dst_smem, const void* src) {
    asm volatile("cp.async.cg.shared.global [%0], [%1], 16;\n"
                 :: "r"(dst_smem), "l"(src) : "memory");
}

__global__ __launch_bounds__(THREADS) void hier_loss_kernel(
    const float* __restrict__ logits,   // [B, 40]
    const int*   __restrict__ labels,   // [B]
    const float* __restrict__ dis,      // [40, 40]
    float* __restrict__ out,            // out[0]=loss, out[1..B]=distance_factor
    int B, int NT)
{
    __shared__ float4 s4[2][NVEC];      // 2 * 1280 * 16 = 40960 B -> 5 blocks/SM
    __shared__ int   s_t;
    __shared__ int   s_last;
    __shared__ float wsum[WARPS];

    const int tid  = threadIdx.x;
    const int lane = tid & 31;
    const int warp = tid >> 5;
    const int r    = tid >> 1;          // row within stage (0..127)
    const int sub  = tid & 1;           // half of row

    const unsigned int sbase = (unsigned int)__cvta_generic_to_shared(&s4[0][0]);

    // ---- stage loader: tile t -> buffer b (identity addressing) ----
    auto prefetch = [&](int t, int b) {
        if (t < NT) {
            long rowsLeft = (long)B - (long)t * TROWS;
            int  nv = (rowsLeft >= TROWS) ? NVEC : (int)rowsLeft * VPR;
            const char* src = (const char*)(logits + (long)t * TROWS * C_DIM);
            unsigned int sb = sbase + (unsigned int)b * (NVEC * 16u);
            #pragma unroll
            for (int j = 0; j < NVEC / THREADS; j++) {   // 5
                int i = tid + j * THREADS;
                if (i < nv)
                    cp_async16(sb + (unsigned int)i * 16u, src + (size_t)i * 16u);
            }
        }
        asm volatile("cp.async.commit_group;\n" ::: "memory");
    };

    auto fetch_label = [&](int t) -> int {
        long row = (long)t * TROWS + r;
        return (t < NT && row < B) ? __ldg(labels + row) : 0;
    };

    // ---- prologue: grab two tiles ----
    if (tid == 0) s_t = atomicAdd(&g_tile_ctr, 1);
    __syncthreads();
    int t_cur = s_t;
    if (tid == 0) s_t = atomicAdd(&g_tile_ctr, 1);
    __syncthreads();
    int t_nxt = s_t;

    prefetch(t_cur, 0);
    int lbl_cur = fetch_label(t_cur);
    int cur = 0;

    float acc = 0.0f;

    while (t_cur < NT) {
        prefetch(t_nxt, cur ^ 1);
        int lbl_nxt = fetch_label(t_nxt);
        if (tid == 0) s_t = atomicAdd(&g_tile_ctr, 1);

        asm volatile("cp.async.wait_group 1;\n" ::: "memory");
        __syncthreads();                       // buf[cur] + s_t visible

        // ---- compute 128 rows from buf[cur], 2 threads per row ----
        {
            const float4* basev = &s4[cur][0] + r * VPR + sub * 5;
            float v[20];
            #pragma unroll
            for (int k = 0; k < 5; k++) {
                float4 q = basev[k];
                v[4 * k + 0] = q.x;
                v[4 * k + 1] = q.y;
                v[4 * k + 2] = q.z;
                v[4 * k + 3] = q.w;
            }

            float mx = v[0];
            int   am = 0;
            #pragma unroll
            for (int i = 1; i < 20; i++) {
                if (v[i] > mx) { mx = v[i]; am = i; }
            }
            am += sub * 20;

            float omx = __shfl_xor_sync(0xFFFFFFFFu, mx, 1);
            int   oam = __shfl_xor_sync(0xFFFFFFFFu, am, 1);
            if (omx > mx || (omx == mx && oam < am)) { mx = omx; am = oam; }

            float ssum = 0.0f;
            #pragma unroll
            for (int i = 0; i < 20; i++) {
                ssum += __expf(v[i] - mx);
            }
            ssum += __shfl_xor_sync(0xFFFFFFFFu, ssum, 1);

            long row = (long)t_cur * TROWS + r;
            if (sub == 0 && row < B) {
                float xl = reinterpret_cast<const float*>(&s4[cur][0])[r * C_DIM + lbl_cur];
                float ce = __logf(ssum) + mx - xl;
                float df = __ldg(dis + lbl_cur * C_DIM + am) + 0.5f;
                out[1 + row] = df;
                acc += ce * df;
            }
        }

        int t_n2 = s_t;
        __syncthreads();                       // done reading buf[cur] / s_t

        t_cur = t_nxt;  lbl_cur = lbl_nxt;
        t_nxt = t_n2;
        cur ^= 1;
    }

    asm volatile("cp.async.wait_group 0;\n" ::: "memory");  // drain before exit

    // ---- block reduction of acc ----
    #pragma unroll
    for (int off = 16; off > 0; off >>= 1)
        acc += __shfl_xor_sync(0xFFFFFFFFu, acc, off);
    if (lane == 0) wsum[warp] = acc;
    __syncthreads();

    if (tid == 0) {
        float t = 0.0f;
        #pragma unroll
        for (int w = 0; w < WARPS; w++) t += wsum[w];
        g_partials[blockIdx.x] = t;
        __threadfence();
        int done = atomicAdd(&g_done_ctr, 1);
        s_last = (done == GRID - 1) ? 1 : 0;
    }
    __syncthreads();

    // ---- last block: reduce partials, write loss, reset counters ----
    if (s_last) {
        float t = 0.0f;
        for (int i = tid; i < GRID; i += THREADS) t += g_partials[i];
        #pragma unroll
        for (int off = 16; off > 0; off >>= 1)
            t += __shfl_xor_sync(0xFFFFFFFFu, t, off);
        if (lane == 0) wsum[warp] = t;
        __syncthreads();
        if (tid == 0) {
            float total = 0.0f;
            #pragma unroll
            for (int w = 0; w < WARPS; w++) total += wsum[w];
            out[0] = total * (1.0f / (float)B);
            g_done_ctr = 0;      // deterministic state for next graph replay
            g_tile_ctr = 0;
        }
    }
}

extern "C" void kernel_launch(void* const* d_in, const int* in_sizes, int n_in,
                              void* d_out, int out_size) {
    const float* logits = (const float*)d_in[0];
    const int*   labels = (const int*)d_in[1];
    const float* dis    = (const float*)d_in[2];
    float* out = (float*)d_out;

    int B  = in_sizes[1];
    int NT = (B + TROWS - 1) / TROWS;

    hier_loss_kernel<<<GRID, THREADS>>>(logits, labels, dis, out, B, NT);
}

// round 15
// speedup vs baseline: 1.1928x; 1.0009x over previous
#include <cuda_runtime.h>
#include <cuda_bf16.h>
#include <cstdint>
#include <math.h>

#define C_DIM    40
#define VPR      10                        // float4 per row (no padding)
#define TROWS    128                       // rows per stage
#define NVEC     (TROWS * VPR)             // 1280 float4 per stage
#define THREADS  256
#define WARPS    (THREADS / 32)
#define SM_COUNT 148
#define BLOCKS_PER_SM 5
#define GRID     (SM_COUNT * BLOCKS_PER_SM)   // 740 persistent blocks

__device__ float g_loss;       // running sum; reset to 0 by last block each launch
__device__ int   g_tile_ctr;   // work-stealing counter; reset each launch
__device__ int   g_done_ctr;   // completion counter; reset each launch

__device__ __forceinline__ void cp_async16(unsigned int dst_smem, const void* src) {
    asm volatile("cp.async.cg.shared.global [%0], [%1], 16;\n"
                 :: "r"(dst_smem), "l"(src) : "memory");
}

__global__ __launch_bounds__(THREADS) void hier_loss_kernel(
    const float* __restrict__ logits,   // [B, 40]
    const int*   __restrict__ labels,   // [B]
    const float* __restrict__ dis,      // [40, 40]
    float* __restrict__ out,            // out[0]=loss, out[1..B]=distance_factor
    int B, int NT)
{
    __shared__ float4 s4[2][NVEC];      // 2 * 1280 * 16 = 40960 B -> 5 blocks/SM
    __shared__ int   s_t;
    __shared__ float wsum[WARPS];

    const int tid  = threadIdx.x;
    const int lane = tid & 31;
    const int warp = tid >> 5;
    const int r    = tid >> 1;          // row within stage (0..127)
    const int sub  = tid & 1;           // half of row

    const unsigned int sbase = (unsigned int)__cvta_generic_to_shared(&s4[0][0]);

    // ---- stage loader: tile t -> buffer b (identity addressing) ----
    auto prefetch = [&](int t, int b) {
        if (t < NT) {
            long rowsLeft = (long)B - (long)t * TROWS;
            int  nv = (rowsLeft >= TROWS) ? NVEC : (int)rowsLeft * VPR;
            const char* src = (const char*)(logits + (long)t * TROWS * C_DIM);
            unsigned int sb = sbase + (unsigned int)b * (NVEC * 16u);
            #pragma unroll
            for (int j = 0; j < NVEC / THREADS; j++) {   // 5
                int i = tid + j * THREADS;
                if (i < nv)
                    cp_async16(sb + (unsigned int)i * 16u, src + (size_t)i * 16u);
            }
        }
        asm volatile("cp.async.commit_group;\n" ::: "memory");
    };

    auto fetch_label = [&](int t) -> int {
        long row = (long)t * TROWS + r;
        return (t < NT && row < B) ? __ldg(labels + row) : 0;
    };

    // ---- prologue: grab two tiles ----
    if (tid == 0) s_t = atomicAdd(&g_tile_ctr, 1);
    __syncthreads();
    int t_cur = s_t;
    if (tid == 0) s_t = atomicAdd(&g_tile_ctr, 1);
    __syncthreads();
    int t_nxt = s_t;

    prefetch(t_cur, 0);
    int lbl_cur = fetch_label(t_cur);
    int cur = 0;

    float acc = 0.0f;

    while (t_cur < NT) {
        prefetch(t_nxt, cur ^ 1);
        int lbl_nxt = fetch_label(t_nxt);
        if (tid == 0) s_t = atomicAdd(&g_tile_ctr, 1);

        asm volatile("cp.async.wait_group 1;\n" ::: "memory");
        __syncthreads();                       // buf[cur] + s_t visible

        // ---- compute 128 rows from buf[cur], 2 threads per row ----
        {
            const float4* basev = &s4[cur][0] + r * VPR + sub * 5;
            float v[20];
            #pragma unroll
            for (int k = 0; k < 5; k++) {
                float4 q = basev[k];
                v[4 * k + 0] = q.x;
                v[4 * k + 1] = q.y;
                v[4 * k + 2] = q.z;
                v[4 * k + 3] = q.w;
            }

            float mx = v[0];
            int   am = 0;
            #pragma unroll
            for (int i = 1; i < 20; i++) {
                if (v[i] > mx) { mx = v[i]; am = i; }
            }
            am += sub * 20;

            float omx = __shfl_xor_sync(0xFFFFFFFFu, mx, 1);
            int   oam = __shfl_xor_sync(0xFFFFFFFFu, am, 1);
            if (omx > mx || (omx == mx && oam < am)) { mx = omx; am = oam; }

            float ssum = 0.0f;
            #pragma unroll
            for (int i = 0; i < 20; i++) {
                ssum += __expf(v[i] - mx);
            }
            ssum += __shfl_xor_sync(0xFFFFFFFFu, ssum, 1);

            long row = (long)t_cur * TROWS + r;
            if (sub == 0 && row < B) {
                float xl = reinterpret_cast<const float*>(&s4[cur][0])[r * C_DIM + lbl_cur];
                float ce = __logf(ssum) + mx - xl;
                float df = __ldg(dis + lbl_cur * C_DIM + am) + 0.5f;
                out[1 + row] = df;
                acc += ce * df;
            }
        }

        int t_n2 = s_t;
        __syncthreads();                       // done reading buf[cur] / s_t

        t_cur = t_nxt;  lbl_cur = lbl_nxt;
        t_nxt = t_n2;
        cur ^= 1;
    }

    asm volatile("cp.async.wait_group 0;\n" ::: "memory");  // drain before exit

    // ---- block reduction of acc, then one atomicAdd into running sum ----
    #pragma unroll
    for (int off = 16; off > 0; off >>= 1)
        acc += __shfl_xor_sync(0xFFFFFFFFu, acc, off);
    if (lane == 0) wsum[warp] = acc;
    __syncthreads();

    if (tid == 0) {
        float t = 0.0f;
        #pragma unroll
        for (int w = 0; w < WARPS; w++) t += wsum[w];
        atomicAdd(&g_loss, t);
        __threadfence();
        int done = atomicAdd(&g_done_ctr, 1);
        if (done == GRID - 1) {
            // last block: finalize and reset state for the next graph replay
            out[0] = g_loss * (1.0f / (float)B);
            g_loss = 0.0f;
            g_done_ctr = 0;
            g_tile_ctr = 0;
        }
    }
}

extern "C" void kernel_launch(void* const* d_in, const int* in_sizes, int n_in,
                              void* d_out, int out_size) {
    const float* logits = (const float*)d_in[0];
    const int*   labels = (const int*)d_in[1];
    const float* dis    = (const float*)d_in[2];
    float* out = (float*)d_out;

    int B  = in_sizes[1];
    int NT = (B + TROWS - 1) / TROWS;

    hier_loss_kernel<<<GRID, THREADS>>>(logits, labels, dis, out, B, NT);
}

// round 16
// speedup vs baseline: 1.2609x; 1.0571x over previous
#include <cuda_runtime.h>
#include <cuda_bf16.h>
#include <cstdint>
#include <math.h>

#define C_DIM    40
#define VPR      10                        // float4 per row (no padding)
#define TROWS    96                        // rows per stage
#define NVEC     (TROWS * VPR)             // 960 float4 per stage
#define THREADS  192
#define WARPS    (THREADS / 32)            // 6
#define SM_COUNT 148
#define BLOCKS_PER_SM 7
#define GRID     (SM_COUNT * BLOCKS_PER_SM)   // 1036 persistent blocks

__device__ float g_loss;       // running sum; reset by last block each launch
__device__ int   g_tile_ctr;   // work-stealing counter; reset each launch
__device__ int   g_done_ctr;   // completion counter; reset each launch

__device__ __forceinline__ void cp_async16(unsigned int dst_smem, const void* src) {
    asm volatile("cp.async.cg.shared.global [%0], [%1], 16;\n"
                 :: "r"(dst_smem), "l"(src) : "memory");
}

__global__ __launch_bounds__(THREADS) void hier_loss_kernel(
    const float* __restrict__ logits,   // [B, 40]
    const int*   __restrict__ labels,   // [B]
    const float* __restrict__ dis,      // [40, 40]
    float* __restrict__ out,            // out[0]=loss, out[1..B]=distance_factor
    int B, int NT)
{
    __shared__ float4 s4[2][NVEC];      // 2 * 960 * 16 = 30720 B -> 7 blocks/SM
    __shared__ int   s_t;
    __shared__ float wsum[WARPS];

    const int tid  = threadIdx.x;
    const int lane = tid & 31;
    const int warp = tid >> 5;
    const int r    = tid >> 1;          // row within stage (0..95)
    const int sub  = tid & 1;           // half of row

    const unsigned int sbase = (unsigned int)__cvta_generic_to_shared(&s4[0][0]);

    // ---- stage loader: tile t -> buffer b (identity addressing) ----
    auto prefetch = [&](int t, int b) {
        if (t < NT) {
            long rowsLeft = (long)B - (long)t * TROWS;
            int  nv = (rowsLeft >= TROWS) ? NVEC : (int)rowsLeft * VPR;
            const char* src = (const char*)(logits + (long)t * TROWS * C_DIM);
            unsigned int sb = sbase + (unsigned int)b * (NVEC * 16u);
            #pragma unroll
            for (int j = 0; j < NVEC / THREADS; j++) {   // 5
                int i = tid + j * THREADS;
                if (i < nv)
                    cp_async16(sb + (unsigned int)i * 16u, src + (size_t)i * 16u);
            }
        }
        asm volatile("cp.async.commit_group;\n" ::: "memory");
    };

    // only the sub==0 lane needs the label
    auto fetch_label = [&](int t) -> int {
        long row = (long)t * TROWS + r;
        return (sub == 0 && t < NT && row < B) ? __ldg(labels + row) : 0;
    };

    // ---- prologue: grab two tiles ----
    if (tid == 0) s_t = atomicAdd(&g_tile_ctr, 1);
    __syncthreads();
    int t_cur = s_t;
    if (tid == 0) s_t = atomicAdd(&g_tile_ctr, 1);
    __syncthreads();
    int t_nxt = s_t;

    prefetch(t_cur, 0);
    int lbl_cur = fetch_label(t_cur);
    int cur = 0;

    float acc = 0.0f;

    while (t_cur < NT) {
        prefetch(t_nxt, cur ^ 1);
        int lbl_nxt = fetch_label(t_nxt);
        if (tid == 0) s_t = atomicAdd(&g_tile_ctr, 1);

        asm volatile("cp.async.wait_group 1;\n" ::: "memory");
        __syncthreads();                       // buf[cur] + s_t visible

        // ---- compute TROWS rows from buf[cur], 2 threads per row ----
        {
            const float4* basev = &s4[cur][0] + r * VPR + sub * 5;
            float v[20];
            #pragma unroll
            for (int k = 0; k < 5; k++) {
                float4 q = basev[k];
                v[4 * k + 0] = q.x;
                v[4 * k + 1] = q.y;
                v[4 * k + 2] = q.z;
                v[4 * k + 3] = q.w;
            }

            float mx = v[0];
            int   am = 0;
            #pragma unroll
            for (int i = 1; i < 20; i++) {
                if (v[i] > mx) { mx = v[i]; am = i; }
            }
            am += sub * 20;

            float omx = __shfl_xor_sync(0xFFFFFFFFu, mx, 1);
            int   oam = __shfl_xor_sync(0xFFFFFFFFu, am, 1);
            if (omx > mx || (omx == mx && oam < am)) { mx = omx; am = oam; }

            float ssum = 0.0f;
            #pragma unroll
            for (int i = 0; i < 20; i++) {
                ssum += __expf(v[i] - mx);
            }
            ssum += __shfl_xor_sync(0xFFFFFFFFu, ssum, 1);

            long row = (long)t_cur * TROWS + r;
            if (sub == 0 && row < B) {
                float xl = reinterpret_cast<const float*>(&s4[cur][0])[r * C_DIM + lbl_cur];
                float ce = __logf(ssum) + mx - xl;
                float df = __ldg(dis + lbl_cur * C_DIM + am) + 0.5f;
                out[1 + row] = df;
                acc += ce * df;
            }
        }

        int t_n2 = s_t;
        __syncthreads();                       // done reading buf[cur] / s_t

        t_cur = t_nxt;  lbl_cur = lbl_nxt;
        t_nxt = t_n2;
        cur ^= 1;
    }

    asm volatile("cp.async.wait_group 0;\n" ::: "memory");  // drain before exit

    // ---- block reduction of acc, then one atomicAdd into running sum ----
    #pragma unroll
    for (int off = 16; off > 0; off >>= 1)
        acc += __shfl_xor_sync(0xFFFFFFFFu, acc, off);
    if (lane == 0) wsum[warp] = acc;
    __syncthreads();

    if (tid == 0) {
        float t = 0.0f;
        #pragma unroll
        for (int w = 0; w < WARPS; w++) t += wsum[w];
        atomicAdd(&g_loss, t);
        __threadfence();
        int done = atomicAdd(&g_done_ctr, 1);
        if (done == GRID - 1) {
            out[0] = g_loss * (1.0f / (float)B);
            g_loss = 0.0f;
            g_done_ctr = 0;
            g_tile_ctr = 0;
        }
    }
}

extern "C" void kernel_launch(void* const* d_in, const int* in_sizes, int n_in,
                              void* d_out, int out_size) {
    const float* logits = (const float*)d_in[0];
    const int*   labels = (const int*)d_in[1];
    const float* dis    = (const float*)d_in[2];
    float* out = (float*)d_out;

    int B  = in_sizes[1];
    int NT = (B + TROWS - 1) / TROWS;

    hier_loss_kernel<<<GRID, THREADS>>>(logits, labels, dis, out, B, NT);
}